// round 1
// baseline (speedup 1.0000x reference)
#include <cuda_runtime.h>

#define HWL   32768          // 32*32*32 spatial positions
#define CDIM  64             // in channels == out channels
#define KPROD 27             // 3*3*3 taps

// Scratch (static __device__ arrays: allocation-free per harness rules)
__device__ float g_xT[HWL * CDIM];            // channels-last x: [s][c]
__device__ float g_wT[KPROD * CDIM * CDIM];   // [k][c][co]

// ---------------------------------------------------------------------------
// Transpose x [c][s] -> g_xT [s][c] via tiled smem transpose (coalesced both ways)
// ---------------------------------------------------------------------------
__global__ void transpose_x_kernel(const float* __restrict__ x) {
    __shared__ float tile[32][33];
    const int sbase = blockIdx.x * 32;
    const int cbase = blockIdx.y * 32;
    const int tx = threadIdx.x, ty = threadIdx.y;
#pragma unroll
    for (int i = 0; i < 4; ++i) {
        int c = ty + i * 8;
        tile[c][tx] = x[(cbase + c) * HWL + sbase + tx];
    }
    __syncthreads();
#pragma unroll
    for (int i = 0; i < 4; ++i) {
        int s = ty + i * 8;
        g_xT[(sbase + s) * CDIM + cbase + tx] = tile[tx][s];
    }
}

// ---------------------------------------------------------------------------
// Transpose weight [co][c][k] -> g_wT [k][c][co]
// ---------------------------------------------------------------------------
__global__ void transpose_w_kernel(const float* __restrict__ w) {
    const int tid = blockIdx.x * blockDim.x + threadIdx.x;
    if (tid >= KPROD * CDIM * CDIM) return;
    const int co = tid & 63;
    const int c  = (tid >> 6) & 63;
    const int k  = tid >> 12;
    g_wT[tid] = w[co * (CDIM * KPROD) + c * KPROD + k];
}

// ---------------------------------------------------------------------------
// Fused deformable conv3d:
//   per CTA: 64 output positions x 64 output channels
//   per tap: Phase A gather+trilinear -> smem sval[c][p]
//            Phase B 4x4 register-tiled GEMM accumulate with sw[c][co]
// ---------------------------------------------------------------------------
__global__ __launch_bounds__(256, 2)
void deform_conv3d_kernel(const float* __restrict__ offset,
                          const float* __restrict__ mask,
                          float* __restrict__ out) {
    __shared__ float sval[CDIM * 64];  // [c][p]  16 KB
    __shared__ float sw  [CDIM * CDIM];// [c][co] 16 KB

    const int t  = threadIdx.x;
    // Phase A mapping: 64 positions x 4 channel-quads (16 ch each)
    const int pA = t & 63;
    const int cq = t >> 6;
    const int pbase = blockIdx.x * 64;
    const int pg = pbase + pA;
    const int lo = pg & 31;
    const int wo = (pg >> 5) & 31;
    const int ho = pg >> 10;

    // Phase B mapping: 16x16 thread grid, 4 positions x 4 cout per thread
    const int pr = t & 15;
    const int cr = t >> 4;

    float acc[4][4];
#pragma unroll
    for (int i = 0; i < 4; ++i)
#pragma unroll
        for (int j = 0; j < 4; ++j) acc[i][j] = 0.f;

    for (int k = 0; k < KPROD; ++k) {
        // ---- stage weights for tap k: contiguous 16 KB slab -> smem ----
        {
            const float4* wsrc = (const float4*)(g_wT + k * (CDIM * CDIM));
            float4* wdst = (float4*)sw;
#pragma unroll
            for (int i = 0; i < 4; ++i) wdst[t + i * 256] = wsrc[t + i * 256];
        }

        // ---- Phase A: sampling coords (recomputed by each of 4 cq threads) ----
        const int ki = k / 9;
        const int kj = (k % 9) / 3;
        const int kk = k % 3;

        const float ch = offset[(k * 3 + 0) * HWL + pg] + (float)(ho - 1 + ki);
        const float cw = offset[(k * 3 + 1) * HWL + pg] + (float)(wo - 1 + kj);
        const float cl = offset[(k * 3 + 2) * HWL + pg] + (float)(lo - 1 + kk);
        const float m  = mask[k * HWL + pg];

        const float hf = floorf(ch), wf = floorf(cw), lf = floorf(cl);
        const int h0 = (int)hf, w0 = (int)wf, l0 = (int)lf;
        const float fh = ch - hf, fw = cw - wf, fl = cl - lf;

        float vacc[16];
#pragma unroll
        for (int i = 0; i < 16; ++i) vacc[i] = 0.f;

#pragma unroll
        for (int cn = 0; cn < 8; ++cn) {
            const int dh = (cn >> 2) & 1, dw = (cn >> 1) & 1, dl = cn & 1;
            const int ih = h0 + dh, iw = w0 + dw, il = l0 + dl;
            const float wt = (dh ? fh : 1.f - fh) *
                             (dw ? fw : 1.f - fw) *
                             (dl ? fl : 1.f - fl);
            if (((unsigned)ih < 32u) && ((unsigned)iw < 32u) && ((unsigned)il < 32u)) {
                const float4* src = (const float4*)(
                    g_xT + (size_t)((((ih << 5) + iw) << 5) + il) * CDIM + cq * 16);
#pragma unroll
                for (int j = 0; j < 4; ++j) {
                    const float4 v = src[j];
                    vacc[j * 4 + 0] += wt * v.x;
                    vacc[j * 4 + 1] += wt * v.y;
                    vacc[j * 4 + 2] += wt * v.z;
                    vacc[j * 4 + 3] += wt * v.w;
                }
            }
        }
        // modulate + stage into smem (coalesced: lanes vary pA)
#pragma unroll
        for (int i = 0; i < 16; ++i)
            sval[(cq * 16 + i) * 64 + pA] = vacc[i] * m;

        __syncthreads();

        // ---- Phase B: rank-1 updates over c ----
#pragma unroll 8
        for (int c = 0; c < CDIM; ++c) {
            const float4 a = *(const float4*)(sval + c * 64 + pr * 4);
            const float4 b = *(const float4*)(sw + c * CDIM + cr * 4);
            acc[0][0] += b.x * a.x; acc[0][1] += b.x * a.y; acc[0][2] += b.x * a.z; acc[0][3] += b.x * a.w;
            acc[1][0] += b.y * a.x; acc[1][1] += b.y * a.y; acc[1][2] += b.y * a.z; acc[1][3] += b.y * a.w;
            acc[2][0] += b.z * a.x; acc[2][1] += b.z * a.y; acc[2][2] += b.z * a.z; acc[2][3] += b.z * a.w;
            acc[3][0] += b.w * a.x; acc[3][1] += b.w * a.y; acc[3][2] += b.w * a.z; acc[3][3] += b.w * a.w;
        }
        __syncthreads();
    }

    // ---- epilogue: out[co][p], float4 along p ----
#pragma unroll
    for (int i = 0; i < 4; ++i) {
        const int co = cr * 4 + i;
        *(float4*)(out + (size_t)co * HWL + pbase + pr * 4) =
            make_float4(acc[i][0], acc[i][1], acc[i][2], acc[i][3]);
    }
}

// ---------------------------------------------------------------------------
extern "C" void kernel_launch(void* const* d_in, const int* in_sizes, int n_in,
                              void* d_out, int out_size) {
    const float* x = nullptr;
    const float* offset = nullptr;
    const float* mask = nullptr;
    const float* weight = nullptr;
    // All input element counts are distinct — bind by size for robustness.
    for (int i = 0; i < n_in; ++i) {
        switch (in_sizes[i]) {
            case 2097152: x      = (const float*)d_in[i]; break;  // [1,64,32,32,32]
            case 2654208: offset = (const float*)d_in[i]; break;  // [1,81,32,32,32]
            case 884736:  mask   = (const float*)d_in[i]; break;  // [1,27,32,32,32]
            case 110592:  weight = (const float*)d_in[i]; break;  // [64,64,3,3,3]
        }
    }

    transpose_x_kernel<<<dim3(1024, 2), dim3(32, 8)>>>(x);
    transpose_w_kernel<<<(KPROD * CDIM * CDIM + 255) / 256, 256>>>(weight);
    deform_conv3d_kernel<<<512, 256>>>(offset, mask, (float*)d_out);
}

// round 3
// speedup vs baseline: 1.1724x; 1.1724x over previous
#include <cuda_runtime.h>

#define HWL    32768          // 32*32*32 spatial positions
#define CDIM   64             // in channels == out channels
#define KPROD  27             // 3*3*3 taps
#define P_TILE 128            // output positions per CTA

// Scratch (static __device__ arrays: allocation-free per harness rules)
__device__ float g_xT[HWL * CDIM];            // channels-last x: [s][c]
__device__ float g_wT[KPROD * CDIM * CDIM];   // [k][c][co]

// ---------------------------------------------------------------------------
// Fused prep: blocks [0,2048) transpose x [c][s] -> g_xT [s][c];
//             blocks [2048,2480) transpose weight [co][c][k] -> g_wT [k][c][co]
// ---------------------------------------------------------------------------
__global__ __launch_bounds__(256) void prep_kernel(const float* __restrict__ x,
                                                   const float* __restrict__ w) {
    const int b = blockIdx.x;
    if (b < 2048) {
        __shared__ float tile[32][33];
        const int sbase = (b & 1023) * 32;
        const int cbase = (b >> 10) * 32;
        const int tx = threadIdx.x & 31, ty = threadIdx.x >> 5;
#pragma unroll
        for (int i = 0; i < 4; ++i) {
            const int c = ty + i * 8;
            tile[c][tx] = x[(cbase + c) * HWL + sbase + tx];
        }
        __syncthreads();
#pragma unroll
        for (int i = 0; i < 4; ++i) {
            const int s = ty + i * 8;
            g_xT[(sbase + s) * CDIM + cbase + tx] = tile[tx][s];
        }
    } else {
        const int tid = (b - 2048) * 256 + threadIdx.x;
        const int co = tid & 63;
        const int c  = (tid >> 6) & 63;
        const int k  = tid >> 12;
        g_wT[tid] = w[co * (CDIM * KPROD) + c * KPROD + k];
    }
}

// ---------------------------------------------------------------------------
// Fused deformable conv3d, CTA tile: 128 positions x 64 cout.
//   Phase A: 128 p x 2 channel-halves, gather+trilinear -> smem sval[c][p]
//   Phase B: 16x16 threads, 8p x 4co register tile, rank-1 GEMM
//   Pipelining: cp.async double-buffered weight slab; offset/mask prefetch.
// ---------------------------------------------------------------------------
__global__ __launch_bounds__(256, 2)
void deform_conv3d_kernel(const float* __restrict__ offset,
                          const float* __restrict__ mask,
                          float* __restrict__ out) {
    extern __shared__ float smem[];
    float* sval = smem;                       // [c][p] 64*128 floats = 32 KB
    float* swbuf[2] = { smem + CDIM * P_TILE,
                        smem + CDIM * P_TILE + CDIM * CDIM };  // 2 x 16 KB

    const int t  = threadIdx.x;
    const int pA = t & 127;
    const int half = t >> 7;
    const int pbase = blockIdx.x * P_TILE;
    const int pg = pbase + pA;
    const int lo = pg & 31;
    const int wo = (pg >> 5) & 31;
    const int ho = pg >> 10;

    const int pr = t & 15;    // 8 positions each
    const int cr = t >> 4;    // 4 cout each

    float acc[8][4];
#pragma unroll
    for (int i = 0; i < 8; ++i)
#pragma unroll
        for (int j = 0; j < 4; ++j) acc[i][j] = 0.f;

    // ---- prologue: async-stage weight slab for tap 0 ----
    {
        const float4* gsrc = (const float4*)g_wT;
#pragma unroll
        for (int i = 0; i < 4; ++i) {
            unsigned sa = (unsigned)__cvta_generic_to_shared(swbuf[0] + (t + i * 256) * 4);
            asm volatile("cp.async.cg.shared.global [%0], [%1], 16;"
                         :: "r"(sa), "l"(gsrc + t + i * 256));
        }
        asm volatile("cp.async.commit_group;");
    }
    // ---- prologue: offsets/mask for tap 0 ----
    float och = offset[0 * HWL + pg];
    float ocw = offset[1 * HWL + pg];
    float ocl = offset[2 * HWL + pg];
    float om  = mask[pg];

    for (int k = 0; k < KPROD; ++k) {
        const int ki = k / 9;
        const int kj = (k % 9) / 3;
        const int kk = k % 3;

        const float ch = och + (float)(ho - 1 + ki);
        const float cw = ocw + (float)(wo - 1 + kj);
        const float cl = ocl + (float)(lo - 1 + kk);
        const float m  = om;

        // prefetch next tap's offsets/mask early (hidden under the gather)
        if (k < KPROD - 1) {
            och = offset[((k + 1) * 3 + 0) * HWL + pg];
            ocw = offset[((k + 1) * 3 + 1) * HWL + pg];
            ocl = offset[((k + 1) * 3 + 2) * HWL + pg];
            om  = mask[(k + 1) * HWL + pg];
        }

        const float hf = floorf(ch), wf = floorf(cw), lf = floorf(cl);
        const int h0 = (int)hf, w0 = (int)wf, l0 = (int)lf;
        const float fh = ch - hf, fw = cw - wf, fl = cl - lf;

        // ---- Phase A: gather + trilinear, 2 passes of 16 channels ----
#pragma unroll
        for (int h2 = 0; h2 < 2; ++h2) {
            const int cb = half * 32 + h2 * 16;
            float vacc[16];
#pragma unroll
            for (int i = 0; i < 16; ++i) vacc[i] = 0.f;
#pragma unroll
            for (int cn = 0; cn < 8; ++cn) {
                const int dh = (cn >> 2) & 1, dw = (cn >> 1) & 1, dl = cn & 1;
                const int ih = h0 + dh, iw = w0 + dw, il = l0 + dl;
                const float wt = (dh ? fh : 1.f - fh) *
                                 (dw ? fw : 1.f - fw) *
                                 (dl ? fl : 1.f - fl);
                if (((unsigned)ih < 32u) & ((unsigned)iw < 32u) & ((unsigned)il < 32u)) {
                    const float4* src = (const float4*)(
                        g_xT + (size_t)((((ih << 5) + iw) << 5) + il) * CDIM + cb);
#pragma unroll
                    for (int j = 0; j < 4; ++j) {
                        const float4 v = src[j];
                        vacc[j * 4 + 0] += wt * v.x;
                        vacc[j * 4 + 1] += wt * v.y;
                        vacc[j * 4 + 2] += wt * v.z;
                        vacc[j * 4 + 3] += wt * v.w;
                    }
                }
            }
#pragma unroll
            for (int i = 0; i < 16; ++i)
                sval[(cb + i) * P_TILE + pA] = vacc[i] * m;
        }

        asm volatile("cp.async.wait_group 0;" ::: "memory");
        __syncthreads();

        // async-stage next tap's weight slab while the GEMM runs
        if (k < KPROD - 1) {
            const float4* gsrc = (const float4*)(g_wT + (size_t)(k + 1) * CDIM * CDIM);
            float* dst = swbuf[(k + 1) & 1];
#pragma unroll
            for (int i = 0; i < 4; ++i) {
                unsigned sa = (unsigned)__cvta_generic_to_shared(dst + (t + i * 256) * 4);
                asm volatile("cp.async.cg.shared.global [%0], [%1], 16;"
                             :: "r"(sa), "l"(gsrc + t + i * 256));
            }
            asm volatile("cp.async.commit_group;");
        }

        // ---- Phase B: rank-1 updates, 8p x 4co per thread ----
        const float* swc = swbuf[k & 1];
#pragma unroll 8
        for (int c = 0; c < CDIM; ++c) {
            const float4 a0 = *(const float4*)(sval + c * P_TILE + pr * 8);
            const float4 a1 = *(const float4*)(sval + c * P_TILE + pr * 8 + 4);
            const float4 b  = *(const float4*)(swc + c * CDIM + cr * 4);
            acc[0][0] += a0.x * b.x; acc[0][1] += a0.x * b.y; acc[0][2] += a0.x * b.z; acc[0][3] += a0.x * b.w;
            acc[1][0] += a0.y * b.x; acc[1][1] += a0.y * b.y; acc[1][2] += a0.y * b.z; acc[1][3] += a0.y * b.w;
            acc[2][0] += a0.z * b.x; acc[2][1] += a0.z * b.y; acc[2][2] += a0.z * b.z; acc[2][3] += a0.z * b.w;
            acc[3][0] += a0.w * b.x; acc[3][1] += a0.w * b.y; acc[3][2] += a0.w * b.z; acc[3][3] += a0.w * b.w;
            acc[4][0] += a1.x * b.x; acc[4][1] += a1.x * b.y; acc[4][2] += a1.x * b.z; acc[4][3] += a1.x * b.w;
            acc[5][0] += a1.y * b.x; acc[5][1] += a1.y * b.y; acc[5][2] += a1.y * b.z; acc[5][3] += a1.y * b.w;
            acc[6][0] += a1.z * b.x; acc[6][1] += a1.z * b.y; acc[6][2] += a1.z * b.z; acc[6][3] += a1.z * b.w;
            acc[7][0] += a1.w * b.x; acc[7][1] += a1.w * b.y; acc[7][2] += a1.w * b.z; acc[7][3] += a1.w * b.w;
        }
        __syncthreads();
    }

    // ---- epilogue: out[co][p], 2 x float4 along p per cout ----
#pragma unroll
    for (int j = 0; j < 4; ++j) {
        const int co = cr * 4 + j;
        float* op = out + (size_t)co * HWL + pbase + pr * 8;
        *(float4*)op       = make_float4(acc[0][j], acc[1][j], acc[2][j], acc[3][j]);
        *(float4*)(op + 4) = make_float4(acc[4][j], acc[5][j], acc[6][j], acc[7][j]);
    }
}

// ---------------------------------------------------------------------------
extern "C" void kernel_launch(void* const* d_in, const int* in_sizes, int n_in,
                              void* d_out, int out_size) {
    const float* x = nullptr;
    const float* offset = nullptr;
    const float* mask = nullptr;
    const float* weight = nullptr;
    for (int i = 0; i < n_in; ++i) {
        switch (in_sizes[i]) {
            case 2097152: x      = (const float*)d_in[i]; break;  // [1,64,32,32,32]
            case 2654208: offset = (const float*)d_in[i]; break;  // [1,81,32,32,32]
            case 884736:  mask   = (const float*)d_in[i]; break;  // [1,27,32,32,32]
            case 110592:  weight = (const float*)d_in[i]; break;  // [64,64,3,3,3]
        }
    }

    // One-time host-side attribute setup (kept out of the capture path).
    static bool s_attr_done = false;
    if (!s_attr_done) {
        cudaFuncSetAttribute(deform_conv3d_kernel,
                             cudaFuncAttributeMaxDynamicSharedMemorySize,
                             (CDIM * P_TILE + 2 * CDIM * CDIM) * (int)sizeof(float));
        s_attr_done = true;
    }

    prep_kernel<<<2480, 256>>>(x, weight);

    const int smem_bytes = (CDIM * P_TILE + 2 * CDIM * CDIM) * sizeof(float);  // 64 KB
    deform_conv3d_kernel<<<HWL / P_TILE, 256, smem_bytes>>>(offset, mask, (float*)d_out);
}

// round 4
// speedup vs baseline: 2.5093x; 2.1404x over previous
#include <cuda_runtime.h>

#define HWL    32768          // 32*32*32 spatial positions
#define CDIM   64             // in channels == out channels
#define KPROD  27             // 3*3*3 taps
#define P_TILE 128            // output positions per CTA

// Scratch (static __device__ arrays: allocation-free per harness rules)
__device__ float g_xT[HWL * CDIM];            // channels-last x: [s][c]
__device__ float g_wT[KPROD * CDIM * CDIM];   // [k][c][co]

// ---------------------------------------------------------------------------
// Fused prep: blocks [0,2048) transpose x [c][s] -> g_xT [s][c];
//             blocks [2048,2480) transpose weight [co][c][k] -> g_wT [k][c][co]
// ---------------------------------------------------------------------------
__global__ __launch_bounds__(256) void prep_kernel(const float* __restrict__ x,
                                                   const float* __restrict__ w) {
    const int b = blockIdx.x;
    if (b < 2048) {
        __shared__ float tile[32][33];
        const int sbase = (b & 1023) * 32;
        const int cbase = (b >> 10) * 32;
        const int tx = threadIdx.x & 31, ty = threadIdx.x >> 5;
#pragma unroll
        for (int i = 0; i < 4; ++i) {
            const int c = ty + i * 8;
            tile[c][tx] = x[(cbase + c) * HWL + sbase + tx];
        }
        __syncthreads();
#pragma unroll
        for (int i = 0; i < 4; ++i) {
            const int s = ty + i * 8;
            g_xT[(sbase + s) * CDIM + cbase + tx] = tile[tx][s];
        }
    } else {
        const int tid = (b - 2048) * 256 + threadIdx.x;
        const int co = tid & 63;
        const int c  = (tid >> 6) & 63;
        const int k  = tid >> 12;
        g_wT[tid] = w[co * (CDIM * KPROD) + c * KPROD + k];
    }
}

// ---------------------------------------------------------------------------
// Fused deformable conv3d, CTA tile: 128 positions x 64 cout.
//
// sval layout (swizzled, [c][p]): word index = c*128 + ((g ^ (c>>2))<<2) + (p&3)
//   where g = p>>2. Swizzle makes both the column-wise STS from the gather and
//   the row-wise float4 LDS in the GEMM (near-)conflict-free.
//
// Phase A (gather): warp w owns positions [w*16, w*16+16). Lane roles:
//   lane16 = lane&15 -> channel quad (c = lane16*4..+3), sub = lane>>4.
//   Coords loaded once per warp (coalesced), shfl-broadcast per position.
//   Each corner fetch: 16 lanes x float4 = 256B contiguous per position.
//
// Phase B (GEMM): prB = t&31 (4 positions prB*4..+3), crB = t>>5 (8 couts).
//   val row read by full warp = 512B conflict-free; w loads warp-uniform.
// ---------------------------------------------------------------------------
__global__ __launch_bounds__(256, 2)
void deform_conv3d_kernel(const float* __restrict__ offset,
                          const float* __restrict__ mask,
                          float* __restrict__ out) {
    extern __shared__ float smem[];
    float* sval = smem;                                 // 64*128 floats, 32 KB
    float* swbuf[2] = { smem + CDIM * P_TILE,
                        smem + CDIM * P_TILE + CDIM * CDIM };  // 2 x 16 KB

    const int t      = threadIdx.x;
    const int lane   = t & 31;
    const int warp   = t >> 5;
    const int lane16 = lane & 15;
    const int sub    = lane >> 4;
    const int pbase  = blockIdx.x * P_TILE;
    const int pw     = warp * 16;                 // warp's position base in tile
    const int myp    = pbase + pw + lane16;       // position whose coords I load

    // Phase B mapping
    const int prB = t & 31;                       // positions prB*4 .. prB*4+3
    const int crB = t >> 5;                       // couts crB*8 .. crB*8+7

    float acc[4][8];
#pragma unroll
    for (int i = 0; i < 4; ++i)
#pragma unroll
        for (int j = 0; j < 8; ++j) acc[i][j] = 0.f;

    // ---- prologue: async-stage weight slab for tap 0 ----
    {
        const float4* gsrc = (const float4*)g_wT;
#pragma unroll
        for (int i = 0; i < 4; ++i) {
            unsigned sa = (unsigned)__cvta_generic_to_shared(swbuf[0] + (t + i * 256) * 4);
            asm volatile("cp.async.cg.shared.global [%0], [%1], 16;"
                         :: "r"(sa), "l"(gsrc + t + i * 256));
        }
        asm volatile("cp.async.commit_group;");
    }

    for (int k = 0; k < KPROD; ++k) {
        const int ki = k / 9;
        const int kj = (k % 9) / 3;
        const int kk = k % 3;

        // coalesced per-warp coord loads (16 positions; lanes 16-31 duplicate)
        const float r_oh = offset[(k * 3 + 0) * HWL + myp];
        const float r_ow = offset[(k * 3 + 1) * HWL + myp];
        const float r_ol = offset[(k * 3 + 2) * HWL + myp];
        const float r_m  = mask[k * HWL + myp];

        // ---- Phase A: 8 iterations x 2 positions per warp ----
#pragma unroll 2
        for (int iter = 0; iter < 8; ++iter) {
            const int idx = iter * 2 + sub;
            const int p   = pw + idx;
            const int pg  = pbase + p;
            const int lo  = pg & 31;
            const int wo  = (pg >> 5) & 31;
            const int ho  = pg >> 10;

            const float och = __shfl_sync(0xffffffffu, r_oh, idx);
            const float ocw = __shfl_sync(0xffffffffu, r_ow, idx);
            const float ocl = __shfl_sync(0xffffffffu, r_ol, idx);
            const float m   = __shfl_sync(0xffffffffu, r_m,  idx);

            const float ch = och + (float)(ho - 1 + ki);
            const float cw = ocw + (float)(wo - 1 + kj);
            const float cl = ocl + (float)(lo - 1 + kk);

            const float hf = floorf(ch), wf = floorf(cw), lf = floorf(cl);
            const int h0 = (int)hf, w0 = (int)wf, l0 = (int)lf;
            const float fh = ch - hf, fw = cw - wf, fl = cl - lf;

            float vx = 0.f, vy = 0.f, vz = 0.f, vw = 0.f;
#pragma unroll
            for (int cn = 0; cn < 8; ++cn) {
                const int dh = (cn >> 2) & 1, dw = (cn >> 1) & 1, dl = cn & 1;
                const int ih = h0 + dh, iw = w0 + dw, il = l0 + dl;
                const float wt = (dh ? fh : 1.f - fh) *
                                 (dw ? fw : 1.f - fw) *
                                 (dl ? fl : 1.f - fl);
                if (((unsigned)ih < 32u) & ((unsigned)iw < 32u) & ((unsigned)il < 32u)) {
                    const float4 g = *(const float4*)(
                        g_xT + (size_t)((((ih << 5) + iw) << 5) + il) * CDIM + lane16 * 4);
                    vx += wt * g.x; vy += wt * g.y; vz += wt * g.z; vw += wt * g.w;
                }
            }
            vx *= m; vy *= m; vz *= m; vw *= m;

            // swizzled column store: channels lane16*4..+3 of position p
            const int col = (((p >> 2) ^ lane16) << 2) + (p & 3);
            float* sp = sval + lane16 * 4 * P_TILE + col;
            sp[0 * P_TILE] = vx;
            sp[1 * P_TILE] = vy;
            sp[2 * P_TILE] = vz;
            sp[3 * P_TILE] = vw;
        }

        asm volatile("cp.async.wait_group 0;" ::: "memory");
        __syncthreads();

        // async-stage next tap's weight slab while the GEMM runs
        if (k < KPROD - 1) {
            const float4* gsrc = (const float4*)(g_wT + (size_t)(k + 1) * CDIM * CDIM);
            float* dst = swbuf[(k + 1) & 1];
#pragma unroll
            for (int i = 0; i < 4; ++i) {
                unsigned sa = (unsigned)__cvta_generic_to_shared(dst + (t + i * 256) * 4);
                asm volatile("cp.async.cg.shared.global [%0], [%1], 16;"
                             :: "r"(sa), "l"(gsrc + t + i * 256));
            }
            asm volatile("cp.async.commit_group;");
        }

        // ---- Phase B: rank-1 updates, 4p x 8co per thread ----
        const float* swc = swbuf[k & 1];
#pragma unroll 4
        for (int c = 0; c < CDIM; ++c) {
            // swizzled row read: granule prB of row c
            const float4 a  = *(const float4*)(sval + c * P_TILE + ((prB ^ (c >> 2)) << 2));
            const float4 b0 = *(const float4*)(swc + c * CDIM + crB * 8);
            const float4 b1 = *(const float4*)(swc + c * CDIM + crB * 8 + 4);
            const float av[4] = { a.x, a.y, a.z, a.w };
            const float bv[8] = { b0.x, b0.y, b0.z, b0.w, b1.x, b1.y, b1.z, b1.w };
#pragma unroll
            for (int i = 0; i < 4; ++i)
#pragma unroll
                for (int j = 0; j < 8; ++j) acc[i][j] += av[i] * bv[j];
        }
        __syncthreads();
    }

    // ---- epilogue: out[co][p], float4 along p; lanes cover 512B contiguous ----
#pragma unroll
    for (int j = 0; j < 8; ++j) {
        const int co = crB * 8 + j;
        *(float4*)(out + (size_t)co * HWL + pbase + prB * 4) =
            make_float4(acc[0][j], acc[1][j], acc[2][j], acc[3][j]);
    }
}

// ---------------------------------------------------------------------------
extern "C" void kernel_launch(void* const* d_in, const int* in_sizes, int n_in,
                              void* d_out, int out_size) {
    const float* x = nullptr;
    const float* offset = nullptr;
    const float* mask = nullptr;
    const float* weight = nullptr;
    for (int i = 0; i < n_in; ++i) {
        switch (in_sizes[i]) {
            case 2097152: x      = (const float*)d_in[i]; break;  // [1,64,32,32,32]
            case 2654208: offset = (const float*)d_in[i]; break;  // [1,81,32,32,32]
            case 884736:  mask   = (const float*)d_in[i]; break;  // [1,27,32,32,32]
            case 110592:  weight = (const float*)d_in[i]; break;  // [64,64,3,3,3]
        }
    }

    // One-time host-side attribute setup (kept out of the capture path).
    static bool s_attr_done = false;
    if (!s_attr_done) {
        cudaFuncSetAttribute(deform_conv3d_kernel,
                             cudaFuncAttributeMaxDynamicSharedMemorySize,
                             (CDIM * P_TILE + 2 * CDIM * CDIM) * (int)sizeof(float));
        s_attr_done = true;
    }

    prep_kernel<<<2480, 256>>>(x, weight);

    const int smem_bytes = (CDIM * P_TILE + 2 * CDIM * CDIM) * sizeof(float);  // 64 KB
    deform_conv3d_kernel<<<HWL / P_TILE, 256, smem_bytes>>>(offset, mask, (float*)d_out);
}

// round 6
// speedup vs baseline: 4.4897x; 1.7892x over previous
#include <cuda_runtime.h>
#include <cuda_bf16.h>
#include <cstdint>

#define HWL    32768          // 32*32*32 spatial positions
#define CDIM   64             // in channels == out channels
#define KPROD  27             // 3*3*3 taps
#define P_TILE 128            // output positions per CTA (= GEMM M)

// Scratch (static __device__ arrays: allocation-free per harness rules)
__device__ float g_xT[HWL * CDIM];                     // channels-last x: [s][c]
__device__ __align__(16) unsigned char g_wb[KPROD * 16384];
// per tap: [b0: 8KB][b1: 8KB]; rows = cout (128B each, 64 c x bf16), SW128-swizzled

__device__ __forceinline__ uint32_t s2u(const void* p) {
    uint32_t a;
    asm("{ .reg .u64 t; cvta.to.shared.u64 t, %1; cvt.u32.u64 %0, t; }"
        : "=r"(a) : "l"(p));
    return a;
}

__device__ __forceinline__ void ldmx4(uint32_t* r, uint32_t addr) {
    asm volatile("ldmatrix.sync.aligned.m8n8.x4.shared.b16 {%0,%1,%2,%3}, [%4];"
                 : "=r"(r[0]), "=r"(r[1]), "=r"(r[2]), "=r"(r[3]) : "r"(addr));
}

__device__ __forceinline__ void mma16816(float* d, const uint32_t* a,
                                         uint32_t b0, uint32_t b1) {
    asm volatile(
        "mma.sync.aligned.m16n8k16.row.col.f32.bf16.bf16.f32 "
        "{%0,%1,%2,%3}, {%4,%5,%6,%7}, {%8,%9}, {%0,%1,%2,%3};"
        : "+f"(d[0]), "+f"(d[1]), "+f"(d[2]), "+f"(d[3])
        : "r"(a[0]), "r"(a[1]), "r"(a[2]), "r"(a[3]), "r"(b0), "r"(b1));
}

// smem layout (bytes from dynamic smem base)
#define OFF_A0 0                     // A split-hi: 128 rows x 128B bf16, SW128
#define OFF_A1 16384                 // A split-lo
#define OFF_W  32768                 // weight stages: 2 x 16KB ([b0 8KB][b1 8KB])
#define SMEM_BYTES (OFF_W + 32768)   // 64 KB

// ---------------------------------------------------------------------------
// Fused prep: blocks [0,2048) transpose x -> g_xT[s][c];
//             blocks [2048,2480) split weight to bf16 hi/lo, pre-swizzled
// ---------------------------------------------------------------------------
__global__ __launch_bounds__(256) void prep_kernel(const float* __restrict__ x,
                                                   const float* __restrict__ w) {
    const int b = blockIdx.x;
    if (b < 2048) {
        __shared__ float tile[32][33];
        const int sbase = (b & 1023) * 32;
        const int cbase = (b >> 10) * 32;
        const int tx = threadIdx.x & 31, ty = threadIdx.x >> 5;
#pragma unroll
        for (int i = 0; i < 4; ++i) {
            const int c = ty + i * 8;
            tile[c][tx] = x[(cbase + c) * HWL + sbase + tx];
        }
        __syncthreads();
#pragma unroll
        for (int i = 0; i < 4; ++i) {
            const int s = ty + i * 8;
            g_xT[(sbase + s) * CDIM + cbase + tx] = tile[tx][s];
        }
    } else {
        const int tid = (b - 2048) * 256 + threadIdx.x;   // < 27*4096 exactly
        const int k   = tid >> 12;
        const int rem = tid & 4095;
        const int co  = rem >> 6;
        const int c   = rem & 63;
        const float v = w[(co * CDIM + c) * KPROD + k];
        const __nv_bfloat16 b0 = __float2bfloat16_rn(v);
        const float r = v - __bfloat162float(b0);
        const __nv_bfloat16 b1 = __float2bfloat16_rn(r);
        const uint32_t off = co * 128 + c * 2;            // row=co, 128B/row
        const uint32_t sw  = off ^ ((off >> 3) & 0x70);   // SW128
        *(__nv_bfloat16*)(g_wb + k * 16384 + sw)        = b0;
        *(__nv_bfloat16*)(g_wb + k * 16384 + 8192 + sw) = b1;
    }
}

// stage one tap's 16KB weight slab (b0|b1) via cp.async (identity copy)
__device__ __forceinline__ void stage_w(uint32_t dst, int k, int t) {
    const char* src = (const char*)g_wb + k * 16384 + t * 16;
    const uint32_t d = dst + t * 16;
#pragma unroll
    for (int i = 0; i < 4; ++i)
        asm volatile("cp.async.cg.shared.global [%0], [%1], 16;"
                     :: "r"(d + i * 4096), "l"(src + i * 4096) : "memory");
    asm volatile("cp.async.commit_group;");
}

// ---------------------------------------------------------------------------
// Fused deformable conv3d with mma.sync bf16 GEMM (double-split, fp32 acc).
//   Gather (8 warps x 16 positions): trilinear in fp32, split to bf16 hi/lo,
//     STS.64 into SW128 A tiles (A0=hi, A1=lo), rows = position (128B).
//   GEMM: warp grid 4(p) x 2(co); each warp 32p x 32co; per k-step:
//     4 ldmatrix.x4 for A (hi+lo x 2 p-tiles), 4 for B (hi+lo x 2 co-pairs),
//     24 mma.sync (3 split terms x 2 p-tiles x 4 co-tiles).
//   Weights double-buffered via cp.async, prefetched a full tap ahead.
// ---------------------------------------------------------------------------
__global__ __launch_bounds__(256, 2)
void deform_conv3d_kernel(const float* __restrict__ offset,
                          const float* __restrict__ mask,
                          float* __restrict__ out) {
    extern __shared__ char smem[];
    const uint32_t sb = s2u(smem);

    const int t      = threadIdx.x;
    const int lane   = t & 31;
    const int warp   = t >> 5;
    const int lane16 = lane & 15;
    const int sub    = lane >> 4;
    const int pbase  = blockIdx.x * P_TILE;
    const int pw     = warp * 16;
    const int myp    = pbase + pw + lane16;

    // GEMM warp tile
    const int pblk = (warp & 3) * 32;
    const int cblk = (warp >> 2) * 32;

    // ldmatrix lane->address precompute (swizzle XOR depends only on row)
    const int lrr = lane & 7;
    // A: group g = lane>>3: row = base + lrr + (g&1)*8 ; col-half = g>>1
    const int a_row_off = lrr + ((lane >> 3) & 1) * 8;
    const int a_colh    = (lane >> 4) & 1;          // 0/1 -> k cols 0-7 / 8-15
    // B: row(co) = base + lrr + ((lane>>4)&1)*8 ; col-half = (lane>>3)&1
    const int b_row_off = lrr + ((lane >> 4) & 1) * 8;
    const int b_colh    = (lane >> 3) & 1;

    uint32_t aAddr[2], bAddr[2];   // per p-tile / per co-pair: base addr sans ks
#pragma unroll
    for (int pt = 0; pt < 2; ++pt) {
        const int r = pblk + pt * 16 + a_row_off;
        aAddr[pt] = (uint32_t)(r * 128) + (uint32_t)(((a_colh * 16) ^ ((r & 7) << 4)));
    }
#pragma unroll
    for (int b2 = 0; b2 < 2; ++b2) {
        const int r = cblk + b2 * 16 + b_row_off;
        bAddr[b2] = (uint32_t)(r * 128) + (uint32_t)(((b_colh * 16) ^ ((r & 7) << 4)));
    }
    // note: adding ks*32 to the column is swizzle-safe (XOR touches bits 4-6 only,
    // ks*32 changes bit 5.. wait 32 = bit5) -> must fold ks into the XOR too:
    // handled below by computing cb ^ sxor per ks explicitly.
    const uint32_t a_sx[2] = { (uint32_t)(((pblk + 0 * 16 + a_row_off) & 7) << 4),
                               (uint32_t)(((pblk + 1 * 16 + a_row_off) & 7) << 4) };
    const uint32_t b_sx[2] = { (uint32_t)(((cblk + 0 * 16 + b_row_off) & 7) << 4),
                               (uint32_t)(((cblk + 1 * 16 + b_row_off) & 7) << 4) };
    const uint32_t a_rb[2] = { (uint32_t)((pblk + 0 * 16 + a_row_off) * 128),
                               (uint32_t)((pblk + 1 * 16 + a_row_off) * 128) };
    const uint32_t b_rb[2] = { (uint32_t)((cblk + 0 * 16 + b_row_off) * 128),
                               (uint32_t)((cblk + 1 * 16 + b_row_off) * 128) };

    float acc[2][4][4];
#pragma unroll
    for (int i = 0; i < 2; ++i)
#pragma unroll
        for (int j = 0; j < 4; ++j)
#pragma unroll
            for (int q = 0; q < 4; ++q) acc[i][j][q] = 0.f;

    // prologue: stage weights for tap 0
    stage_w(sb + OFF_W, 0, t);

    for (int k = 0; k < KPROD; ++k) {
        // prefetch next tap's weights immediately (lands during this gather)
        if (k < KPROD - 1)
            stage_w(sb + OFF_W + (uint32_t)((k + 1) & 1) * 16384, k + 1, t);

        const int ki = k / 9;
        const int kj = (k % 9) / 3;
        const int kk = k % 3;

        const float r_oh = offset[(k * 3 + 0) * HWL + myp];
        const float r_ow = offset[(k * 3 + 1) * HWL + myp];
        const float r_ol = offset[(k * 3 + 2) * HWL + myp];
        const float r_m  = mask[k * HWL + myp];

        // ---- gather: 8 iterations x 2 positions per warp ----
#pragma unroll 2
        for (int iter = 0; iter < 8; ++iter) {
            const int idx = iter * 2 + sub;
            const int p   = pw + idx;
            const int pg  = pbase + p;
            const int lo  = pg & 31;
            const int wo  = (pg >> 5) & 31;
            const int ho  = pg >> 10;

            const float och = __shfl_sync(0xffffffffu, r_oh, idx);
            const float ocw = __shfl_sync(0xffffffffu, r_ow, idx);
            const float ocl = __shfl_sync(0xffffffffu, r_ol, idx);
            const float m   = __shfl_sync(0xffffffffu, r_m,  idx);

            const float ch = och + (float)(ho - 1 + ki);
            const float cw = ocw + (float)(wo - 1 + kj);
            const float cl = ocl + (float)(lo - 1 + kk);

            const float hf = floorf(ch), wf = floorf(cw), lf = floorf(cl);
            const int h0 = (int)hf, w0 = (int)wf, l0 = (int)lf;
            const float fh = ch - hf, fw = cw - wf, fl = cl - lf;

            float vx = 0.f, vy = 0.f, vz = 0.f, vw = 0.f;
#pragma unroll
            for (int cn = 0; cn < 8; ++cn) {
                const int dh = (cn >> 2) & 1, dw = (cn >> 1) & 1, dl = cn & 1;
                const int ih = h0 + dh, iw = w0 + dw, il = l0 + dl;
                const float wt = (dh ? fh : 1.f - fh) *
                                 (dw ? fw : 1.f - fw) *
                                 (dl ? fl : 1.f - fl);
                if (((unsigned)ih < 32u) & ((unsigned)iw < 32u) & ((unsigned)il < 32u)) {
                    const float4 g = *(const float4*)(
                        g_xT + (size_t)((((ih << 5) + iw) << 5) + il) * CDIM + lane16 * 4);
                    vx += wt * g.x; vy += wt * g.y; vz += wt * g.z; vw += wt * g.w;
                }
            }
            vx *= m; vy *= m; vz *= m; vw *= m;

            const __nv_bfloat16 hx = __float2bfloat16_rn(vx);
            const __nv_bfloat16 hy = __float2bfloat16_rn(vy);
            const __nv_bfloat16 hz = __float2bfloat16_rn(vz);
            const __nv_bfloat16 hw = __float2bfloat16_rn(vw);
            const __nv_bfloat16 lx = __float2bfloat16_rn(vx - __bfloat162float(hx));
            const __nv_bfloat16 ly = __float2bfloat16_rn(vy - __bfloat162float(hy));
            const __nv_bfloat16 lz = __float2bfloat16_rn(vz - __bfloat162float(hz));
            const __nv_bfloat16 lw = __float2bfloat16_rn(vw - __bfloat162float(hw));

            uint2 phi, plo;
            phi.x = (uint32_t)__bfloat16_as_ushort(hx) | ((uint32_t)__bfloat16_as_ushort(hy) << 16);
            phi.y = (uint32_t)__bfloat16_as_ushort(hz) | ((uint32_t)__bfloat16_as_ushort(hw) << 16);
            plo.x = (uint32_t)__bfloat16_as_ushort(lx) | ((uint32_t)__bfloat16_as_ushort(ly) << 16);
            plo.y = (uint32_t)__bfloat16_as_ushort(lz) | ((uint32_t)__bfloat16_as_ushort(lw) << 16);

            // SW128-swizzled store: row = p (128B), cols = 4 channels (8B)
            const uint32_t off = (uint32_t)(p * 128 + lane16 * 8);
            const uint32_t sw  = off ^ (uint32_t)((p & 7) << 4);
            *(uint2*)(smem + OFF_A0 + sw) = phi;
            *(uint2*)(smem + OFF_A1 + sw) = plo;
        }

        // weights for tap k must be resident before GEMM
        if (k == KPROD - 1)
            asm volatile("cp.async.wait_group 0;" ::: "memory");
        else
            asm volatile("cp.async.wait_group 1;" ::: "memory");
        __syncthreads();

        // ---- GEMM: tap k ----
        const uint32_t wS = sb + OFF_W + (uint32_t)(k & 1) * 16384;
        const uint32_t a0b = sb + OFF_A0, a1b = sb + OFF_A1;
#pragma unroll
        for (int ks = 0; ks < 4; ++ks) {
            const uint32_t cbA = ((uint32_t)(ks * 32 + a_colh * 16));
            const uint32_t cbB = ((uint32_t)(ks * 32 + b_colh * 16));
            uint32_t A0[2][4], A1[2][4], B0[2][4], B1[2][4];
#pragma unroll
            for (int pt = 0; pt < 2; ++pt) {
                const uint32_t ad = a_rb[pt] + (cbA ^ a_sx[pt]);
                ldmx4(A0[pt], a0b + ad);
                ldmx4(A1[pt], a1b + ad);
            }
#pragma unroll
            for (int b2 = 0; b2 < 2; ++b2) {
                const uint32_t bd = b_rb[b2] + (cbB ^ b_sx[b2]);
                ldmx4(B0[b2], wS + bd);
                ldmx4(B1[b2], wS + 8192 + bd);
            }
#pragma unroll
            for (int pt = 0; pt < 2; ++pt)
#pragma unroll
                for (int bt = 0; bt < 4; ++bt) {
                    const int b2 = bt >> 1, hh = (bt & 1) * 2;
                    mma16816(acc[pt][bt], A0[pt], B0[b2][hh], B0[b2][hh + 1]);
                    mma16816(acc[pt][bt], A0[pt], B1[b2][hh], B1[b2][hh + 1]);
                    mma16816(acc[pt][bt], A1[pt], B0[b2][hh], B0[b2][hh + 1]);
                }
        }
        __syncthreads();
    }

    // ---- epilogue: D frag layout -> out[co][p] ----
    const int prow = lane >> 2;
    const int pcol = (lane & 3) * 2;
#pragma unroll
    for (int pt = 0; pt < 2; ++pt)
#pragma unroll
        for (int bt = 0; bt < 4; ++bt) {
            const int p0 = pbase + pblk + pt * 16 + prow;
            const int co = cblk + bt * 8 + pcol;
            out[(size_t)co * HWL + p0]           = acc[pt][bt][0];
            out[(size_t)(co + 1) * HWL + p0]     = acc[pt][bt][1];
            out[(size_t)co * HWL + p0 + 8]       = acc[pt][bt][2];
            out[(size_t)(co + 1) * HWL + p0 + 8] = acc[pt][bt][3];
        }
}

// ---------------------------------------------------------------------------
extern "C" void kernel_launch(void* const* d_in, const int* in_sizes, int n_in,
                              void* d_out, int out_size) {
    const float* x = nullptr;
    const float* offset = nullptr;
    const float* mask = nullptr;
    const float* weight = nullptr;
    for (int i = 0; i < n_in; ++i) {
        switch (in_sizes[i]) {
            case 2097152: x      = (const float*)d_in[i]; break;  // [1,64,32,32,32]
            case 2654208: offset = (const float*)d_in[i]; break;  // [1,81,32,32,32]
            case 884736:  mask   = (const float*)d_in[i]; break;  // [1,27,32,32,32]
            case 110592:  weight = (const float*)d_in[i]; break;  // [64,64,3,3,3]
        }
    }

    static bool s_attr_done = false;
    if (!s_attr_done) {
        cudaFuncSetAttribute(deform_conv3d_kernel,
                             cudaFuncAttributeMaxDynamicSharedMemorySize, SMEM_BYTES);
        s_attr_done = true;
    }

    prep_kernel<<<2480, 256>>>(x, weight);
    deform_conv3d_kernel<<<HWL / P_TILE, 256, SMEM_BYTES>>>(offset, mask, (float*)d_out);
}

// round 7
// speedup vs baseline: 4.6748x; 1.0412x over previous
#include <cuda_runtime.h>
#include <cuda_bf16.h>
#include <cstdint>

#define HWL    32768          // 32*32*32 spatial positions
#define CDIM   64             // in channels == out channels
#define KPROD  27             // 3*3*3 taps
#define P_TILE 128            // output positions per CTA (= GEMM M)

// Scratch (static __device__ arrays: allocation-free per harness rules)
__device__ float g_xT[HWL * CDIM];                     // channels-last x: [s][c]
__device__ __align__(16) unsigned char g_wb[KPROD * 16384];
// per tap: [b0: 8KB][b1: 8KB]; rows = cout (128B each, 64 c x bf16), SW128-swizzled

__device__ __forceinline__ uint32_t s2u(const void* p) {
    uint32_t a;
    asm("{ .reg .u64 t; cvta.to.shared.u64 t, %1; cvt.u32.u64 %0, t; }"
        : "=r"(a) : "l"(p));
    return a;
}

__device__ __forceinline__ void ldmx4(uint32_t* r, uint32_t addr) {
    asm volatile("ldmatrix.sync.aligned.m8n8.x4.shared.b16 {%0,%1,%2,%3}, [%4];"
                 : "=r"(r[0]), "=r"(r[1]), "=r"(r[2]), "=r"(r[3]) : "r"(addr));
}

__device__ __forceinline__ void mma16816(float* d, const uint32_t* a,
                                         uint32_t b0, uint32_t b1) {
    asm volatile(
        "mma.sync.aligned.m16n8k16.row.col.f32.bf16.bf16.f32 "
        "{%0,%1,%2,%3}, {%4,%5,%6,%7}, {%8,%9}, {%0,%1,%2,%3};"
        : "+f"(d[0]), "+f"(d[1]), "+f"(d[2]), "+f"(d[3])
        : "r"(a[0]), "r"(a[1]), "r"(a[2]), "r"(a[3]), "r"(b0), "r"(b1));
}

// smem layout (bytes from dynamic smem base)
// A buffers: 2 x [hi 16KB | lo 16KB] = 64 KB ; weights: 2 x 16KB = 32 KB
#define OFF_A      0
#define A_BUF_SZ   32768
#define A_LO       16384
#define OFF_W      65536
#define SMEM_BYTES (OFF_W + 32768)   // 96 KB -> 2 CTAs/SM (192 KB)

// ---------------------------------------------------------------------------
// Fused prep: blocks [0,2048) transpose x -> g_xT[s][c];
//             blocks [2048,2480) split weight to bf16 hi/lo, pre-swizzled
// ---------------------------------------------------------------------------
__global__ __launch_bounds__(256) void prep_kernel(const float* __restrict__ x,
                                                   const float* __restrict__ w) {
    const int b = blockIdx.x;
    if (b < 2048) {
        __shared__ float tile[32][33];
        const int sbase = (b & 1023) * 32;
        const int cbase = (b >> 10) * 32;
        const int tx = threadIdx.x & 31, ty = threadIdx.x >> 5;
#pragma unroll
        for (int i = 0; i < 4; ++i) {
            const int c = ty + i * 8;
            tile[c][tx] = x[(cbase + c) * HWL + sbase + tx];
        }
        __syncthreads();
#pragma unroll
        for (int i = 0; i < 4; ++i) {
            const int s = ty + i * 8;
            g_xT[(sbase + s) * CDIM + cbase + tx] = tile[tx][s];
        }
    } else {
        const int tid = (b - 2048) * 256 + threadIdx.x;   // < 27*4096 exactly
        const int k   = tid >> 12;
        const int rem = tid & 4095;
        const int co  = rem >> 6;
        const int c   = rem & 63;
        const float v = w[(co * CDIM + c) * KPROD + k];
        const __nv_bfloat16 b0 = __float2bfloat16_rn(v);
        const float r = v - __bfloat162float(b0);
        const __nv_bfloat16 b1 = __float2bfloat16_rn(r);
        const uint32_t off = co * 128 + c * 2;            // row=co, 128B/row
        const uint32_t sw  = off ^ ((off >> 3) & 0x70);   // SW128
        *(__nv_bfloat16*)(g_wb + k * 16384 + sw)        = b0;
        *(__nv_bfloat16*)(g_wb + k * 16384 + 8192 + sw) = b1;
    }
}

// stage one tap's 16KB weight slab (b0|b1) via cp.async (identity copy)
__device__ __forceinline__ void stage_w(uint32_t dst, int k, int t) {
    const char* src = (const char*)g_wb + k * 16384 + t * 16;
    const uint32_t d = dst + t * 16;
#pragma unroll
    for (int i = 0; i < 4; ++i)
        asm volatile("cp.async.cg.shared.global [%0], [%1], 16;"
                     :: "r"(d + i * 4096), "l"(src + i * 4096) : "memory");
    asm volatile("cp.async.commit_group;");
}

// ---------------------------------------------------------------------------
// Gather one tap into an A buffer (hi/lo bf16 splits, SW128 rows = position).
// Warp owns 16 positions; lane16 -> 4 channels; 2 positions per iteration.
// ---------------------------------------------------------------------------
__device__ __forceinline__ void gather_tap(
    char* smem, uint32_t abase, int k,
    const float* __restrict__ offset, const float* __restrict__ mask,
    int myp, int pw, int sub, int lane16, int pbase)
{
    const int ki = k / 9;
    const int kj = (k % 9) / 3;
    const int kk = k % 3;

    const float r_oh = offset[(k * 3 + 0) * HWL + myp];
    const float r_ow = offset[(k * 3 + 1) * HWL + myp];
    const float r_ol = offset[(k * 3 + 2) * HWL + myp];
    const float r_m  = mask[k * HWL + myp];

#pragma unroll 2
    for (int iter = 0; iter < 8; ++iter) {
        const int idx = iter * 2 + sub;
        const int p   = pw + idx;
        const int pg  = pbase + p;
        const int lo  = pg & 31;
        const int wo  = (pg >> 5) & 31;
        const int ho  = pg >> 10;

        const float och = __shfl_sync(0xffffffffu, r_oh, idx);
        const float ocw = __shfl_sync(0xffffffffu, r_ow, idx);
        const float ocl = __shfl_sync(0xffffffffu, r_ol, idx);
        const float m   = __shfl_sync(0xffffffffu, r_m,  idx);

        const float ch = och + (float)(ho - 1 + ki);
        const float cw = ocw + (float)(wo - 1 + kj);
        const float cl = ocl + (float)(lo - 1 + kk);

        const float hf = floorf(ch), wf = floorf(cw), lf = floorf(cl);
        const int h0 = (int)hf, w0 = (int)wf, l0 = (int)lf;
        const float fh = ch - hf, fw = cw - wf, fl = cl - lf;

        float vx = 0.f, vy = 0.f, vz = 0.f, vw = 0.f;
#pragma unroll
        for (int cn = 0; cn < 8; ++cn) {
            const int dh = (cn >> 2) & 1, dw = (cn >> 1) & 1, dl = cn & 1;
            const int ih = h0 + dh, iw = w0 + dw, il = l0 + dl;
            const float wt = (dh ? fh : 1.f - fh) *
                             (dw ? fw : 1.f - fw) *
                             (dl ? fl : 1.f - fl);
            if (((unsigned)ih < 32u) & ((unsigned)iw < 32u) & ((unsigned)il < 32u)) {
                const float4 g = *(const float4*)(
                    g_xT + (size_t)((((ih << 5) + iw) << 5) + il) * CDIM + lane16 * 4);
                vx += wt * g.x; vy += wt * g.y; vz += wt * g.z; vw += wt * g.w;
            }
        }
        vx *= m; vy *= m; vz *= m; vw *= m;

        const __nv_bfloat16 hx = __float2bfloat16_rn(vx);
        const __nv_bfloat16 hy = __float2bfloat16_rn(vy);
        const __nv_bfloat16 hz = __float2bfloat16_rn(vz);
        const __nv_bfloat16 hw = __float2bfloat16_rn(vw);
        const __nv_bfloat16 lx = __float2bfloat16_rn(vx - __bfloat162float(hx));
        const __nv_bfloat16 ly = __float2bfloat16_rn(vy - __bfloat162float(hy));
        const __nv_bfloat16 lz = __float2bfloat16_rn(vz - __bfloat162float(hz));
        const __nv_bfloat16 lw = __float2bfloat16_rn(vw - __bfloat162float(hw));

        uint2 phi, plo;
        phi.x = (uint32_t)__bfloat16_as_ushort(hx) | ((uint32_t)__bfloat16_as_ushort(hy) << 16);
        phi.y = (uint32_t)__bfloat16_as_ushort(hz) | ((uint32_t)__bfloat16_as_ushort(hw) << 16);
        plo.x = (uint32_t)__bfloat16_as_ushort(lx) | ((uint32_t)__bfloat16_as_ushort(ly) << 16);
        plo.y = (uint32_t)__bfloat16_as_ushort(lz) | ((uint32_t)__bfloat16_as_ushort(lw) << 16);

        const uint32_t off = (uint32_t)(p * 128 + lane16 * 8);
        const uint32_t sw  = off ^ (uint32_t)((p & 7) << 4);
        *(uint2*)(smem + abase + sw)        = phi;
        *(uint2*)(smem + abase + A_LO + sw) = plo;
    }
}

// ---------------------------------------------------------------------------
// Fused deformable conv3d, software-pipelined:
//   iteration k: gather(tap k+1 -> A buf (k+1)&1)  [memory pipes]
//                GEMM  (tap k    from A buf k&1)   [tensor + LDS pipes]
//                one __syncthreads
//   -> gather latency of warp i hides under MMA work of warp j.
// ---------------------------------------------------------------------------
__global__ __launch_bounds__(256, 2)
void deform_conv3d_kernel(const float* __restrict__ offset,
                          const float* __restrict__ mask,
                          float* __restrict__ out) {
    extern __shared__ char smem[];
    const uint32_t sb = s2u(smem);

    const int t      = threadIdx.x;
    const int lane   = t & 31;
    const int warp   = t >> 5;
    const int lane16 = lane & 15;
    const int sub    = lane >> 4;
    const int pbase  = blockIdx.x * P_TILE;
    const int pw     = warp * 16;
    const int myp    = pbase + pw + lane16;

    // GEMM warp tile: 4(p) x 2(co) warp grid, 32p x 32co per warp
    const int pblk = (warp & 3) * 32;
    const int cblk = (warp >> 2) * 32;

    const int lrr = lane & 7;
    const int a_row_off = lrr + ((lane >> 3) & 1) * 8;
    const int a_colh    = (lane >> 4) & 1;
    const int b_row_off = lrr + ((lane >> 4) & 1) * 8;
    const int b_colh    = (lane >> 3) & 1;

    const uint32_t a_sx[2] = { (uint32_t)(((pblk + 0 * 16 + a_row_off) & 7) << 4),
                               (uint32_t)(((pblk + 1 * 16 + a_row_off) & 7) << 4) };
    const uint32_t b_sx[2] = { (uint32_t)(((cblk + 0 * 16 + b_row_off) & 7) << 4),
                               (uint32_t)(((cblk + 1 * 16 + b_row_off) & 7) << 4) };
    const uint32_t a_rb[2] = { (uint32_t)((pblk + 0 * 16 + a_row_off) * 128),
                               (uint32_t)((pblk + 1 * 16 + a_row_off) * 128) };
    const uint32_t b_rb[2] = { (uint32_t)((cblk + 0 * 16 + b_row_off) * 128),
                               (uint32_t)((cblk + 1 * 16 + b_row_off) * 128) };

    float acc[2][4][4];
#pragma unroll
    for (int i = 0; i < 2; ++i)
#pragma unroll
        for (int j = 0; j < 4; ++j)
#pragma unroll
            for (int q = 0; q < 4; ++q) acc[i][j][q] = 0.f;

    // prologue: weights tap 0 + gather tap 0 into buffer 0
    stage_w(sb + OFF_W, 0, t);
    gather_tap(smem, OFF_A, 0, offset, mask, myp, pw, sub, lane16, pbase);
    __syncthreads();

    for (int k = 0; k < KPROD; ++k) {
        // prefetch next tap's weights + gather next tap (other A buffer).
        // No sync before GEMM: it reads buffer k&1, gather writes (k+1)&1.
        if (k < KPROD - 1) {
            stage_w(sb + OFF_W + (uint32_t)((k + 1) & 1) * 16384, k + 1, t);
            gather_tap(smem, OFF_A + (uint32_t)((k + 1) & 1) * A_BUF_SZ, k + 1,
                       offset, mask, myp, pw, sub, lane16, pbase);
        }

        // weights for tap k must be resident before GEMM
        if (k == KPROD - 1)
            asm volatile("cp.async.wait_group 0;" ::: "memory");
        else
            asm volatile("cp.async.wait_group 1;" ::: "memory");

        // ---- GEMM: tap k ----
        const uint32_t wS  = sb + OFF_W + (uint32_t)(k & 1) * 16384;
        const uint32_t a0b = sb + OFF_A + (uint32_t)(k & 1) * A_BUF_SZ;
        const uint32_t a1b = a0b + A_LO;
#pragma unroll
        for (int ks = 0; ks < 4; ++ks) {
            const uint32_t cbA = ((uint32_t)(ks * 32 + a_colh * 16));
            const uint32_t cbB = ((uint32_t)(ks * 32 + b_colh * 16));
            uint32_t A0[2][4], A1[2][4], B0[2][4], B1[2][4];
#pragma unroll
            for (int pt = 0; pt < 2; ++pt) {
                const uint32_t ad = a_rb[pt] + (cbA ^ a_sx[pt]);
                ldmx4(A0[pt], a0b + ad);
                ldmx4(A1[pt], a1b + ad);
            }
#pragma unroll
            for (int b2 = 0; b2 < 2; ++b2) {
                const uint32_t bd = b_rb[b2] + (cbB ^ b_sx[b2]);
                ldmx4(B0[b2], wS + bd);
                ldmx4(B1[b2], wS + 8192 + bd);
            }
#pragma unroll
            for (int pt = 0; pt < 2; ++pt)
#pragma unroll
                for (int bt = 0; bt < 4; ++bt) {
                    const int b2 = bt >> 1, hh = (bt & 1) * 2;
                    mma16816(acc[pt][bt], A0[pt], B0[b2][hh], B0[b2][hh + 1]);
                    mma16816(acc[pt][bt], A0[pt], B1[b2][hh], B1[b2][hh + 1]);
                    mma16816(acc[pt][bt], A1[pt], B0[b2][hh], B0[b2][hh + 1]);
                }
        }
        __syncthreads();
    }

    // ---- epilogue: D frag layout -> out[co][p] ----
    const int prow = lane >> 2;
    const int pcol = (lane & 3) * 2;
#pragma unroll
    for (int pt = 0; pt < 2; ++pt)
#pragma unroll
        for (int bt = 0; bt < 4; ++bt) {
            const int p0 = pbase + pblk + pt * 16 + prow;
            const int co = cblk + bt * 8 + pcol;
            out[(size_t)co * HWL + p0]           = acc[pt][bt][0];
            out[(size_t)(co + 1) * HWL + p0]     = acc[pt][bt][1];
            out[(size_t)co * HWL + p0 + 8]       = acc[pt][bt][2];
            out[(size_t)(co + 1) * HWL + p0 + 8] = acc[pt][bt][3];
        }
}

// ---------------------------------------------------------------------------
extern "C" void kernel_launch(void* const* d_in, const int* in_sizes, int n_in,
                              void* d_out, int out_size) {
    const float* x = nullptr;
    const float* offset = nullptr;
    const float* mask = nullptr;
    const float* weight = nullptr;
    for (int i = 0; i < n_in; ++i) {
        switch (in_sizes[i]) {
            case 2097152: x      = (const float*)d_in[i]; break;  // [1,64,32,32,32]
            case 2654208: offset = (const float*)d_in[i]; break;  // [1,81,32,32,32]
            case 884736:  mask   = (const float*)d_in[i]; break;  // [1,27,32,32,32]
            case 110592:  weight = (const float*)d_in[i]; break;  // [64,64,3,3,3]
        }
    }

    static bool s_attr_done = false;
    if (!s_attr_done) {
        cudaFuncSetAttribute(deform_conv3d_kernel,
                             cudaFuncAttributeMaxDynamicSharedMemorySize, SMEM_BYTES);
        s_attr_done = true;
    }

    prep_kernel<<<2480, 256>>>(x, weight);
    deform_conv3d_kernel<<<HWL / P_TILE, 256, SMEM_BYTES>>>(offset, mask, (float*)d_out);
}